// round 13
// baseline (speedup 1.0000x reference)
#include <cuda_runtime.h>
#include <cuda_bf16.h>
#include <math.h>
#include <cstdint>

#define L_TOTAL 2048
#define D_MODEL 2048
#define D_HEAD  128
#define N_HEADS 16
#define QKV_COLS (3 * D_MODEL)   // 6144
#define EPS 1e-6f
#define SM_SCALE 0.08838834764831845f   // 1/sqrt(128)

// ---------------- scratch (device globals: allocation-free rule) ------------
__device__ float g_qkv[(size_t)L_TOTAL * QKV_COLS];   // [L, 6144] = q|k|v (fp32)
__device__ float g_attn[(size_t)L_TOTAL * D_MODEL];   // [L, 2048]  (fp32)

__device__ __nv_bfloat16 g_xhi[(size_t)L_TOTAL * D_MODEL];
__device__ __nv_bfloat16 g_xlo[(size_t)L_TOTAL * D_MODEL];
__device__ __nv_bfloat16 g_wqkv_hi[(size_t)QKV_COLS * D_MODEL];
__device__ __nv_bfloat16 g_wqkv_lo[(size_t)QKV_COLS * D_MODEL];
__device__ __nv_bfloat16 g_wp_hi[(size_t)D_MODEL * D_MODEL];
__device__ __nv_bfloat16 g_wp_lo[(size_t)D_MODEL * D_MODEL];
__device__ __nv_bfloat16 g_ahi[(size_t)L_TOTAL * D_MODEL];
__device__ __nv_bfloat16 g_alo[(size_t)L_TOTAL * D_MODEL];

// =================== helpers ================================================
__device__ __forceinline__ uint32_t smem_to_u32(const void* p) {
    uint32_t a;
    asm("{ .reg .u64 t; cvta.to.shared.u64 t, %1; cvt.u32.u64 %0, t; }"
        : "=r"(a) : "l"(p));
    return a;
}

__device__ __forceinline__ void ldsm_x4(uint32_t* r, uint32_t addr) {
    asm volatile("ldmatrix.sync.aligned.m8n8.x4.shared.b16 {%0,%1,%2,%3}, [%4];"
                 : "=r"(r[0]), "=r"(r[1]), "=r"(r[2]), "=r"(r[3]) : "r"(addr));
}

__device__ __forceinline__ void mma_bf16(float* c, const uint32_t* a,
                                         uint32_t b0, uint32_t b1) {
    asm volatile(
        "mma.sync.aligned.m16n8k16.row.col.f32.bf16.bf16.f32 "
        "{%0,%1,%2,%3}, {%4,%5,%6,%7}, {%8,%9}, {%0,%1,%2,%3};\n"
        : "+f"(c[0]), "+f"(c[1]), "+f"(c[2]), "+f"(c[3])
        : "r"(a[0]), "r"(a[1]), "r"(a[2]), "r"(a[3]), "r"(b0), "r"(b1));
}

__device__ __forceinline__ void cp16(uint32_t saddr, const void* gaddr) {
    asm volatile("cp.async.cg.shared.global [%0], [%1], 16;"
                 :: "r"(saddr), "l"(gaddr));
}
#define CP_COMMIT() asm volatile("cp.async.commit_group;" ::: "memory")
#define CP_WAIT2()  asm volatile("cp.async.wait_group 2;" ::: "memory")

// =================== split fp32 -> bf16 hi + bf16 lo ========================
__global__ __launch_bounds__(256) void split_bf16_kernel(
    const float* __restrict__ src,
    __nv_bfloat16* __restrict__ hi, __nv_bfloat16* __restrict__ lo, int n4)
{
    const int i = blockIdx.x * 256 + threadIdx.x;
    if (i >= n4) return;
    const float4 v = ((const float4*)src)[i];
    __nv_bfloat16 h0 = __float2bfloat16(v.x);
    __nv_bfloat16 h1 = __float2bfloat16(v.y);
    __nv_bfloat16 h2 = __float2bfloat16(v.z);
    __nv_bfloat16 h3 = __float2bfloat16(v.w);
    __nv_bfloat16 l0 = __float2bfloat16(v.x - __bfloat162float(h0));
    __nv_bfloat16 l1 = __float2bfloat16(v.y - __bfloat162float(h1));
    __nv_bfloat16 l2 = __float2bfloat16(v.z - __bfloat162float(h2));
    __nv_bfloat16 l3 = __float2bfloat16(v.w - __bfloat162float(h3));
    __nv_bfloat162 hp0; hp0.x = h0; hp0.y = h1;
    __nv_bfloat162 hp1; hp1.x = h2; hp1.y = h3;
    __nv_bfloat162 lp0; lp0.x = l0; lp0.y = l1;
    __nv_bfloat162 lp1; lp1.x = l2; lp1.y = l3;
    ((__nv_bfloat162*)hi)[2 * i]     = hp0;
    ((__nv_bfloat162*)hi)[2 * i + 1] = hp1;
    ((__nv_bfloat162*)lo)[2 * i]     = lp0;
    ((__nv_bfloat162*)lo)[2 * i + 1] = lp1;
}

// =================== HMMA split-bf16 GEMM (cp.async 4-stage, fixed) =========
// C[M,N] = A[M,K] @ B[N,K]^T + bias, via hi*hi + hi*lo + lo*hi (fp32 accum).
// CTA: 128x128 tile, 256 thr = 8 warps (2m x 4n), warp tile 64x32. BK=32.
// Per-chunk ordering: issue(c+3) -> commit -> compute(c) -> wait_group 2 ->
// __syncthreads().  The barrier AFTER the wait is what makes other threads'
// cp.async results visible before they are consumed.
#define SMS 80                       // bytes per smem row
#define MATB (128 * SMS)             // 10240 B per operand tile
#define STAGEB (4 * MATB)            // 40960 B per stage (Ah|Al|Bh|Bl)
#define NSTAGE 4
#define GEMM_SMEM (NSTAGE * STAGEB)  // 163840 B

__global__ __launch_bounds__(256) void gemm_mma(
    const __nv_bfloat16* __restrict__ Ahi, const __nv_bfloat16* __restrict__ Alo,
    const __nv_bfloat16* __restrict__ Bhi, const __nv_bfloat16* __restrict__ Blo,
    const float* __restrict__ bias, float* __restrict__ C, int N, int K)
{
    extern __shared__ __align__(16) char sm[];

    const int tid = threadIdx.x;
    const int lane = tid & 31, wid = tid >> 5;
    const int warp_m = wid >> 2, warp_n = wid & 3;
    const int m0 = blockIdx.y * 128, n0 = blockIdx.x * 128;

    const __nv_bfloat16* srcs[4];
    srcs[0] = Ahi + (size_t)m0 * K;
    srcs[1] = Alo + (size_t)m0 * K;
    srcs[2] = Bhi + (size_t)n0 * K;
    srcs[3] = Blo + (size_t)n0 * K;

    // per-thread load slots: e = tid + j*256; row = e>>2, q = e&3 (16B units)
    const int r_lo = tid >> 2,          q_lo = tid & 3;
    const int r_hi = (tid + 256) >> 2,  q_hi = tid & 3;   // rows 64..127

    const uint32_t sbase = smem_to_u32(sm);

    float acc[4][4][4];
    #pragma unroll
    for (int a = 0; a < 4; ++a)
        #pragma unroll
        for (int b = 0; b < 4; ++b)
            #pragma unroll
            for (int cc = 0; cc < 4; ++cc) acc[a][b][cc] = 0.f;

    // ldmatrix base addresses (per thread, stage 0)
    const int lrow = lane & 15;
    const int lcol = (lane >> 4) * 16;
    uint32_t aAddrH[4], aAddrL[4], bAddrH[2], bAddrL[2];
    #pragma unroll
    for (int mf = 0; mf < 4; ++mf) {
        const int r = warp_m * 64 + mf * 16 + lrow;
        aAddrH[mf] = sbase + 0 * MATB + r * SMS + lcol;
        aAddrL[mf] = sbase + 1 * MATB + r * SMS + lcol;
    }
    #pragma unroll
    for (int np = 0; np < 2; ++np) {
        const int r = warp_n * 32 + np * 16 + lrow;
        bAddrH[np] = sbase + 2 * MATB + r * SMS + lcol;
        bAddrL[np] = sbase + 3 * MATB + r * SMS + lcol;
    }

    // cp.async store offsets (per thread)
    const uint32_t s_lo = (uint32_t)(r_lo * SMS + q_lo * 16);
    const uint32_t s_hi = (uint32_t)(r_hi * SMS + q_hi * 16);

    const int nch = K >> 5;   // BK = 32

    // prologue: stages 0..2 issued + committed
    #pragma unroll
    for (int st = 0; st < NSTAGE - 1; ++st) {
        const int k0 = st << 5;
        const uint32_t sb = sbase + st * STAGEB;
        #pragma unroll
        for (int s = 0; s < 4; ++s) {
            cp16(sb + s * MATB + s_lo, srcs[s] + (size_t)r_lo * K + k0 + q_lo * 8);
            cp16(sb + s * MATB + s_hi, srcs[s] + (size_t)r_hi * K + k0 + q_hi * 8);
        }
        CP_COMMIT();
    }
    CP_WAIT2();          // stage 0 complete (this thread)
    __syncthreads();     // stage 0 complete (all threads)

    for (int c = 0; c < nch; ++c) {
        // issue loads for stage c+3 into buffer (c+3)&3 == (c-1)&3
        // (safe: stage c-1 reads finished before the barrier that ended iter c-1)
        if (c + NSTAGE - 1 < nch) {
            const int k0 = (c + NSTAGE - 1) << 5;
            const uint32_t sb = sbase + ((c + NSTAGE - 1) & (NSTAGE - 1)) * STAGEB;
            #pragma unroll
            for (int s = 0; s < 4; ++s) {
                cp16(sb + s * MATB + s_lo, srcs[s] + (size_t)r_lo * K + k0 + q_lo * 8);
                cp16(sb + s * MATB + s_hi, srcs[s] + (size_t)r_hi * K + k0 + q_hi * 8);
            }
        }
        CP_COMMIT();     // empty group at tail keeps wait_group arithmetic exact

        // compute stage c (resident, all-threads visible)
        const uint32_t stoff = (uint32_t)((c & (NSTAGE - 1)) * STAGEB);
        #pragma unroll
        for (int ks = 0; ks < 2; ++ks) {
            uint32_t ah[4][4], al[4][4];
            #pragma unroll
            for (int mf = 0; mf < 4; ++mf) {
                ldsm_x4(ah[mf], aAddrH[mf] + stoff + ks * 32);
                ldsm_x4(al[mf], aAddrL[mf] + stoff + ks * 32);
            }
            #pragma unroll
            for (int np = 0; np < 2; ++np) {
                uint32_t bh[4], bl[4];
                ldsm_x4(bh, bAddrH[np] + stoff + ks * 32);
                ldsm_x4(bl, bAddrL[np] + stoff + ks * 32);
                #pragma unroll
                for (int half = 0; half < 2; ++half) {
                    const int nf = np * 2 + half;
                    const uint32_t bh0 = bh[half], bh1 = bh[half + 2];
                    const uint32_t bl0 = bl[half], bl1 = bl[half + 2];
                    #pragma unroll
                    for (int mf = 0; mf < 4; ++mf) {
                        mma_bf16(acc[mf][nf], ah[mf], bh0, bh1);
                        mma_bf16(acc[mf][nf], ah[mf], bl0, bl1);
                        mma_bf16(acc[mf][nf], al[mf], bh0, bh1);
                    }
                }
            }
        }

        CP_WAIT2();       // stage c+1 complete (this thread)
        __syncthreads();  // stage c+1 complete + visible (all threads)
    }

    // epilogue
    const int trow = lane >> 2;
    const int tcol = (lane & 3) * 2;
    #pragma unroll
    for (int mf = 0; mf < 4; ++mf) {
        #pragma unroll
        for (int nf = 0; nf < 4; ++nf) {
            const int r   = m0 + warp_m * 64 + mf * 16 + trow;
            const int col = n0 + warp_n * 32 + nf * 8 + tcol;
            const float b0 = bias[col], b1 = bias[col + 1];
            float2 v0, v1;
            v0.x = acc[mf][nf][0] + b0; v0.y = acc[mf][nf][1] + b1;
            v1.x = acc[mf][nf][2] + b0; v1.y = acc[mf][nf][3] + b1;
            *(float2*)&C[(size_t)r * N + col]       = v0;
            *(float2*)&C[(size_t)(r + 8) * N + col] = v1;
        }
    }
}

// ---------------- RMSNorm + RoPE, in place on q and k heads -----------------
__global__ __launch_bounds__(128) void norm_rope_kernel(
    const float* __restrict__ pe,
    const float* __restrict__ q_scale,
    const float* __restrict__ k_scale)
{
    const int t  = blockIdx.x;
    const int hh = blockIdx.y;
    const bool isK = hh >= N_HEADS;
    const int h  = hh & (N_HEADS - 1);
    const int d  = threadIdx.x;

    float* base = g_qkv + (size_t)t * QKV_COLS + (isK ? D_MODEL : 0) + h * D_HEAD;

    float v = base[d];
    float sq = v * v;
    #pragma unroll
    for (int o = 16; o > 0; o >>= 1)
        sq += __shfl_xor_sync(0xffffffffu, sq, o);

    __shared__ float red[4];
    __shared__ float sn[D_HEAD];
    const int wid = d >> 5;
    if ((d & 31) == 0) red[wid] = sq;
    __syncthreads();
    const float tot = red[0] + red[1] + red[2] + red[3];
    const float rrms = rsqrtf(tot * (1.f / D_HEAD) + EPS);

    const float* sc = isK ? k_scale : q_scale;
    sn[d] = v * rrms * sc[d];
    __syncthreads();

    const float c = pe[(size_t)t * 256 + (d & ~1)];
    const float s = pe[(size_t)t * 256 + 128 + (d & ~1)];
    const float v0 = sn[d & ~1];
    const float v1 = sn[d | 1];
    base[d] = (d & 1) ? (v0 * s + v1 * c) : (v0 * c - v1 * s);
}

// ---------------- flash-tile attention ------------------------------------
#define QS_STRIDE 72
#define PN_STRIDE 72

struct AttnSmem {
    float Qs[128 * QS_STRIDE];
    union {
        float Ks[128 * QS_STRIDE];
        float Vs[64 * 128];
    } kv;
    float Pn[64 * PN_STRIDE];
    float m[64], l[64], newm[64], cf[64];
};

__global__ __launch_bounds__(256, 2) void attn_tile_kernel(const int* __restrict__ seq_lens)
{
    extern __shared__ char smem_raw[];
    AttnSmem& S = *reinterpret_cast<AttnSmem*>(smem_raw);

    const int tid = threadIdx.x;
    const int tx = tid & 15;
    const int ty = tid >> 4;
    const int qt = blockIdx.x;
    const int h  = blockIdx.y;
    const int q0 = qt * 64;
    const int r0 = ty * 4;
    const int c0 = tx * 4;

    int start = 0, len = 0;
    #pragma unroll
    for (int i = 0; i < 4; ++i) {
        len = seq_lens[i];
        if (q0 < start + len) break;
        start += len;
    }
    const int end = start + len;

    for (int e = tid; e < 64 * 128; e += 256) {
        const int r = e >> 7, d = e & 127;
        S.Qs[d * QS_STRIDE + r] =
            g_qkv[(size_t)(q0 + r) * QKV_COLS + h * D_HEAD + d];
    }
    if (tid < 64) { S.m[tid] = -INFINITY; S.l[tid] = 0.f; }

    float o[4][8];
    #pragma unroll
    for (int i = 0; i < 4; ++i)
        #pragma unroll
        for (int c = 0; c < 8; ++c) o[i][c] = 0.f;

    for (int j0 = start; j0 < end; j0 += 64) {
        __syncthreads();

        for (int e = tid; e < 64 * 128; e += 256) {
            const int r = e >> 7, d = e & 127;
            S.kv.Ks[d * QS_STRIDE + r] =
                g_qkv[(size_t)(j0 + r) * QKV_COLS + D_MODEL + h * D_HEAD + d];
        }
        __syncthreads();

        float s[4][4];
        #pragma unroll
        for (int i = 0; i < 4; ++i)
            #pragma unroll
            for (int j = 0; j < 4; ++j) s[i][j] = 0.f;

        #pragma unroll 8
        for (int kk = 0; kk < 128; ++kk) {
            const float4 a = *(const float4*)&S.Qs[kk * QS_STRIDE + r0];
            const float4 b = *(const float4*)&S.kv.Ks[kk * QS_STRIDE + c0];
            const float av[4] = {a.x, a.y, a.z, a.w};
            const float bv[4] = {b.x, b.y, b.z, b.w};
            #pragma unroll
            for (int i = 0; i < 4; ++i)
                #pragma unroll
                for (int j = 0; j < 4; ++j)
                    s[i][j] = fmaf(av[i], bv[j], s[i][j]);
        }
        #pragma unroll
        for (int i = 0; i < 4; ++i)
            #pragma unroll
            for (int j = 0; j < 4; ++j) s[i][j] *= SM_SCALE;

        float rmax[4];
        #pragma unroll
        for (int i = 0; i < 4; ++i) {
            float v = fmaxf(fmaxf(s[i][0], s[i][1]), fmaxf(s[i][2], s[i][3]));
            #pragma unroll
            for (int off = 8; off > 0; off >>= 1)
                v = fmaxf(v, __shfl_xor_sync(0xffffffffu, v, off));
            rmax[i] = v;
        }
        if (tx == 0) {
            #pragma unroll
            for (int i = 0; i < 4; ++i) {
                const float mo = S.m[r0 + i];
                const float mn = fmaxf(mo, rmax[i]);
                S.newm[r0 + i] = mn;
                S.cf[r0 + i]   = __expf(mo - mn);
                S.m[r0 + i]    = mn;
            }
        }
        __syncthreads();

        float rs[4];
        #pragma unroll
        for (int i = 0; i < 4; ++i) {
            const float mn = S.newm[r0 + i];
            #pragma unroll
            for (int j = 0; j < 4; ++j) s[i][j] = __expf(s[i][j] - mn);
            rs[i] = (s[i][0] + s[i][1]) + (s[i][2] + s[i][3]);
            #pragma unroll
            for (int off = 8; off > 0; off >>= 1)
                rs[i] += __shfl_xor_sync(0xffffffffu, rs[i], off);
        }
        if (tx == 0) {
            #pragma unroll
            for (int i = 0; i < 4; ++i)
                S.l[r0 + i] = S.l[r0 + i] * S.cf[r0 + i] + rs[i];
        }
        #pragma unroll
        for (int i = 0; i < 4; ++i) {
            float4 pv = make_float4(s[i][0], s[i][1], s[i][2], s[i][3]);
            *(float4*)&S.Pn[(r0 + i) * PN_STRIDE + c0] = pv;
        }
        for (int e = tid; e < 64 * 128; e += 256) {
            const int r = e >> 7, d = e & 127;
            S.kv.Vs[r * 128 + d] =
                g_qkv[(size_t)(j0 + r) * QKV_COLS + 2 * D_MODEL + h * D_HEAD + d];
        }
        __syncthreads();

        {
            float cfl[4];
            #pragma unroll
            for (int i = 0; i < 4; ++i) cfl[i] = S.cf[r0 + i];
            #pragma unroll
            for (int i = 0; i < 4; ++i)
                #pragma unroll
                for (int c = 0; c < 8; ++c) o[i][c] *= cfl[i];
        }

        for (int j = 0; j < 64; j += 4) {
            float p[4][4];
            #pragma unroll
            for (int i = 0; i < 4; ++i) {
                const float4 p4 = *(const float4*)&S.Pn[(r0 + i) * PN_STRIDE + j];
                p[i][0] = p4.x; p[i][1] = p4.y; p[i][2] = p4.z; p[i][3] = p4.w;
            }
            #pragma unroll
            for (int jj = 0; jj < 4; ++jj) {
                const float4 v0 = *(const float4*)&S.kv.Vs[(j + jj) * 128 + tx * 8];
                const float4 v1 = *(const float4*)&S.kv.Vs[(j + jj) * 128 + tx * 8 + 4];
                #pragma unroll
                for (int i = 0; i < 4; ++i) {
                    o[i][0] = fmaf(p[i][jj], v0.x, o[i][0]);
                    o[i][1] = fmaf(p[i][jj], v0.y, o[i][1]);
                    o[i][2] = fmaf(p[i][jj], v0.z, o[i][2]);
                    o[i][3] = fmaf(p[i][jj], v0.w, o[i][3]);
                    o[i][4] = fmaf(p[i][jj], v1.x, o[i][4]);
                    o[i][5] = fmaf(p[i][jj], v1.y, o[i][5]);
                    o[i][6] = fmaf(p[i][jj], v1.z, o[i][6]);
                    o[i][7] = fmaf(p[i][jj], v1.w, o[i][7]);
                }
            }
        }
    }

    #pragma unroll
    for (int i = 0; i < 4; ++i) {
        const float linv = 1.f / S.l[r0 + i];
        float* dst = g_attn + (size_t)(q0 + r0 + i) * D_MODEL + h * D_HEAD + tx * 8;
        float4 w0, w1;
        w0.x = o[i][0] * linv; w0.y = o[i][1] * linv;
        w0.z = o[i][2] * linv; w0.w = o[i][3] * linv;
        w1.x = o[i][4] * linv; w1.y = o[i][5] * linv;
        w1.z = o[i][6] * linv; w1.w = o[i][7] * linv;
        *(float4*)(dst)     = w0;
        *(float4*)(dst + 4) = w1;
    }
}

// ---------------------------------------------------------------------------
extern "C" void kernel_launch(void* const* d_in, const int* in_sizes, int n_in,
                              void* d_out, int out_size)
{
    const float* x        = (const float*)d_in[0];
    const float* pe       = (const float*)d_in[1];
    const int*   seq_lens = (const int*)  d_in[2];
    const float* qkv_w    = (const float*)d_in[3];
    const float* qkv_b    = (const float*)d_in[4];
    const float* q_scale  = (const float*)d_in[5];
    const float* k_scale  = (const float*)d_in[6];
    const float* proj_w   = (const float*)d_in[7];
    const float* proj_b   = (const float*)d_in[8];
    float* out = (float*)d_out;

    float *qkv_ptr = nullptr, *attn_ptr = nullptr;
    __nv_bfloat16 *xhi, *xlo, *wqh, *wql, *wph, *wpl, *ahi, *alo;
    cudaGetSymbolAddress((void**)&qkv_ptr,  g_qkv);
    cudaGetSymbolAddress((void**)&attn_ptr, g_attn);
    cudaGetSymbolAddress((void**)&xhi, g_xhi);
    cudaGetSymbolAddress((void**)&xlo, g_xlo);
    cudaGetSymbolAddress((void**)&wqh, g_wqkv_hi);
    cudaGetSymbolAddress((void**)&wql, g_wqkv_lo);
    cudaGetSymbolAddress((void**)&wph, g_wp_hi);
    cudaGetSymbolAddress((void**)&wpl, g_wp_lo);
    cudaGetSymbolAddress((void**)&ahi, g_ahi);
    cudaGetSymbolAddress((void**)&alo, g_alo);

    const int attn_smem = (int)sizeof(AttnSmem);
    cudaFuncSetAttribute(attn_tile_kernel,
                         cudaFuncAttributeMaxDynamicSharedMemorySize, attn_smem);
    cudaFuncSetAttribute(gemm_mma,
                         cudaFuncAttributeMaxDynamicSharedMemorySize, GEMM_SMEM);

    // 0) split inputs into bf16 hi/lo
    {
        const int n4x = (L_TOTAL * D_MODEL) / 4;      // 1M
        const int n4w = (QKV_COLS * D_MODEL) / 4;     // 3M
        split_bf16_kernel<<<n4x / 256, 256>>>(x, xhi, xlo, n4x);
        split_bf16_kernel<<<n4w / 256, 256>>>(qkv_w, wqh, wql, n4w);
        split_bf16_kernel<<<n4x / 256, 256>>>(proj_w, wph, wpl, n4x);
    }

    // 1) qkv = x @ qkv_w^T + qkv_b   (HMMA, split-bf16 3-pass, async pipeline)
    gemm_mma<<<dim3(QKV_COLS / 128, L_TOTAL / 128), 256, GEMM_SMEM>>>(
        xhi, xlo, wqh, wql, qkv_b, qkv_ptr, QKV_COLS, D_MODEL);

    // 2) RMSNorm + RoPE in place on q, k
    norm_rope_kernel<<<dim3(L_TOTAL, 2 * N_HEADS), 128>>>(pe, q_scale, k_scale);

    // 3) block-diagonal flash-tile attention -> g_attn
    attn_tile_kernel<<<dim3(L_TOTAL / 64, N_HEADS), 256, attn_smem>>>(seq_lens);

    // 4) split attention output, then out = attn @ proj_w^T + proj_b
    {
        const int n4a = (L_TOTAL * D_MODEL) / 4;
        split_bf16_kernel<<<n4a / 256, 256>>>(attn_ptr, ahi, alo, n4a);
    }
    gemm_mma<<<dim3(D_MODEL / 128, L_TOTAL / 128), 256, GEMM_SMEM>>>(
        ahi, alo, wph, wpl, proj_b, out, D_MODEL, D_MODEL);
}

// round 14
// speedup vs baseline: 1.6935x; 1.6935x over previous
#include <cuda_runtime.h>
#include <cuda_bf16.h>
#include <math.h>
#include <cstdint>

#define L_TOTAL 2048
#define D_MODEL 2048
#define D_HEAD  128
#define N_HEADS 16
#define QKV_COLS (3 * D_MODEL)   // 6144
#define EPS 1e-6f
#define SM_SCALE 0.08838834764831845f   // 1/sqrt(128)

// ---------------- scratch (device globals: allocation-free rule) ------------
__device__ float g_qkv[(size_t)L_TOTAL * QKV_COLS];   // [L, 6144] = q|k|v (fp32)
__device__ float g_attn[(size_t)L_TOTAL * D_MODEL];   // [L, 2048]  (fp32)

__device__ __nv_bfloat16 g_xhi[(size_t)L_TOTAL * D_MODEL];
__device__ __nv_bfloat16 g_xlo[(size_t)L_TOTAL * D_MODEL];
__device__ __nv_bfloat16 g_wqkv_hi[(size_t)QKV_COLS * D_MODEL];
__device__ __nv_bfloat16 g_wqkv_lo[(size_t)QKV_COLS * D_MODEL];
__device__ __nv_bfloat16 g_wp_hi[(size_t)D_MODEL * D_MODEL];
__device__ __nv_bfloat16 g_wp_lo[(size_t)D_MODEL * D_MODEL];
__device__ __nv_bfloat16 g_ahi[(size_t)L_TOTAL * D_MODEL];
__device__ __nv_bfloat16 g_alo[(size_t)L_TOTAL * D_MODEL];

// =================== helpers ================================================
__device__ __forceinline__ uint32_t smem_to_u32(const void* p) {
    uint32_t a;
    asm("{ .reg .u64 t; cvta.to.shared.u64 t, %1; cvt.u32.u64 %0, t; }"
        : "=r"(a) : "l"(p));
    return a;
}

__device__ __forceinline__ void ldsm_x4(uint32_t* r, uint32_t addr) {
    asm volatile("ldmatrix.sync.aligned.m8n8.x4.shared.b16 {%0,%1,%2,%3}, [%4];"
                 : "=r"(r[0]), "=r"(r[1]), "=r"(r[2]), "=r"(r[3]) : "r"(addr));
}

__device__ __forceinline__ void mma_bf16(float* c, const uint32_t* a,
                                         uint32_t b0, uint32_t b1) {
    asm volatile(
        "mma.sync.aligned.m16n8k16.row.col.f32.bf16.bf16.f32 "
        "{%0,%1,%2,%3}, {%4,%5,%6,%7}, {%8,%9}, {%0,%1,%2,%3};\n"
        : "+f"(c[0]), "+f"(c[1]), "+f"(c[2]), "+f"(c[3])
        : "r"(a[0]), "r"(a[1]), "r"(a[2]), "r"(a[3]), "r"(b0), "r"(b1));
}

__device__ __forceinline__ void cp16(uint32_t saddr, const void* gaddr) {
    asm volatile("cp.async.cg.shared.global [%0], [%1], 16;"
                 :: "r"(saddr), "l"(gaddr));
}
#define CP_COMMIT() asm volatile("cp.async.commit_group;" ::: "memory")
#define CP_WAIT0()  asm volatile("cp.async.wait_group 0;" ::: "memory")

// =================== split fp32 -> bf16 hi + bf16 lo ========================
__global__ __launch_bounds__(256) void split_bf16_kernel(
    const float* __restrict__ src,
    __nv_bfloat16* __restrict__ hi, __nv_bfloat16* __restrict__ lo, int n4)
{
    const int i = blockIdx.x * 256 + threadIdx.x;
    if (i >= n4) return;
    const float4 v = ((const float4*)src)[i];
    __nv_bfloat16 h0 = __float2bfloat16(v.x);
    __nv_bfloat16 h1 = __float2bfloat16(v.y);
    __nv_bfloat16 h2 = __float2bfloat16(v.z);
    __nv_bfloat16 h3 = __float2bfloat16(v.w);
    __nv_bfloat16 l0 = __float2bfloat16(v.x - __bfloat162float(h0));
    __nv_bfloat16 l1 = __float2bfloat16(v.y - __bfloat162float(h1));
    __nv_bfloat16 l2 = __float2bfloat16(v.z - __bfloat162float(h2));
    __nv_bfloat16 l3 = __float2bfloat16(v.w - __bfloat162float(h3));
    __nv_bfloat162 hp0; hp0.x = h0; hp0.y = h1;
    __nv_bfloat162 hp1; hp1.x = h2; hp1.y = h3;
    __nv_bfloat162 lp0; lp0.x = l0; lp0.y = l1;
    __nv_bfloat162 lp1; lp1.x = l2; lp1.y = l3;
    ((__nv_bfloat162*)hi)[2 * i]     = hp0;
    ((__nv_bfloat162*)hi)[2 * i + 1] = hp1;
    ((__nv_bfloat162*)lo)[2 * i]     = lp0;
    ((__nv_bfloat162*)lo)[2 * i + 1] = lp1;
}

// =================== HMMA split-bf16 GEMM (cp.async 2-stage, 2 CTA/SM) ======
// C[M,N] = A[M,K] @ B[N,K]^T + bias, via hi*hi + hi*lo + lo*hi (fp32 accum).
// CTA: 128x128 tile, 256 thr = 8 warps (2m x 4n), warp tile 64x32. BK=32.
// Per-chunk: issue(c+1) -> commit -> compute(c) -> wait_group 0 -> barrier.
// 2 stages x 40KB = 80KB smem; __launch_bounds__(256,2) caps regs at 128 so
// two CTAs co-reside per SM and hide each other's wait/barrier tails.
#define SMS 80                       // bytes per smem row
#define MATB (128 * SMS)             // 10240 B per operand tile
#define STAGEB (4 * MATB)            // 40960 B per stage (Ah|Al|Bh|Bl)
#define NSTAGE 2
#define GEMM_SMEM (NSTAGE * STAGEB)  // 81920 B

__global__ __launch_bounds__(256, 2) void gemm_mma(
    const __nv_bfloat16* __restrict__ Ahi, const __nv_bfloat16* __restrict__ Alo,
    const __nv_bfloat16* __restrict__ Bhi, const __nv_bfloat16* __restrict__ Blo,
    const float* __restrict__ bias, float* __restrict__ C, int N, int K)
{
    extern __shared__ __align__(16) char sm[];

    const int tid = threadIdx.x;
    const int lane = tid & 31, wid = tid >> 5;
    const int warp_m = wid >> 2, warp_n = wid & 3;
    const int m0 = blockIdx.y * 128, n0 = blockIdx.x * 128;

    const __nv_bfloat16* srcs[4];
    srcs[0] = Ahi + (size_t)m0 * K;
    srcs[1] = Alo + (size_t)m0 * K;
    srcs[2] = Bhi + (size_t)n0 * K;
    srcs[3] = Blo + (size_t)n0 * K;

    // per-thread load slots: e = tid + j*256; row = e>>2, q = e&3 (16B units)
    const int r_lo = tid >> 2,          q_lo = tid & 3;
    const int r_hi = (tid + 256) >> 2,  q_hi = tid & 3;   // rows 64..127

    const uint32_t sbase = smem_to_u32(sm);

    float acc[4][4][4];
    #pragma unroll
    for (int a = 0; a < 4; ++a)
        #pragma unroll
        for (int b = 0; b < 4; ++b)
            #pragma unroll
            for (int cc = 0; cc < 4; ++cc) acc[a][b][cc] = 0.f;

    // ldmatrix base addresses (per thread, stage 0)
    const int lrow = lane & 15;
    const int lcol = (lane >> 4) * 16;
    uint32_t aAddrH[4], aAddrL[4], bAddrH[2], bAddrL[2];
    #pragma unroll
    for (int mf = 0; mf < 4; ++mf) {
        const int r = warp_m * 64 + mf * 16 + lrow;
        aAddrH[mf] = sbase + 0 * MATB + r * SMS + lcol;
        aAddrL[mf] = sbase + 1 * MATB + r * SMS + lcol;
    }
    #pragma unroll
    for (int np = 0; np < 2; ++np) {
        const int r = warp_n * 32 + np * 16 + lrow;
        bAddrH[np] = sbase + 2 * MATB + r * SMS + lcol;
        bAddrL[np] = sbase + 3 * MATB + r * SMS + lcol;
    }

    // cp.async store offsets (per thread)
    const uint32_t s_lo = (uint32_t)(r_lo * SMS + q_lo * 16);
    const uint32_t s_hi = (uint32_t)(r_hi * SMS + q_hi * 16);

    const int nch = K >> 5;   // BK = 32

    // prologue: stage 0
    {
        #pragma unroll
        for (int s = 0; s < 4; ++s) {
            cp16(sbase + s * MATB + s_lo, srcs[s] + (size_t)r_lo * K + q_lo * 8);
            cp16(sbase + s * MATB + s_hi, srcs[s] + (size_t)r_hi * K + q_hi * 8);
        }
        CP_COMMIT();
    }
    CP_WAIT0();
    __syncthreads();     // stage 0 resident + visible to all threads

    for (int c = 0; c < nch; ++c) {
        // issue loads for stage c+1 into the other buffer (safe: the barrier
        // ending iter c-1 followed all reads of that buffer)
        if (c + 1 < nch) {
            const int k0 = (c + 1) << 5;
            const uint32_t sb = sbase + ((c + 1) & 1) * STAGEB;
            #pragma unroll
            for (int s = 0; s < 4; ++s) {
                cp16(sb + s * MATB + s_lo, srcs[s] + (size_t)r_lo * K + k0 + q_lo * 8);
                cp16(sb + s * MATB + s_hi, srcs[s] + (size_t)r_hi * K + k0 + q_hi * 8);
            }
        }
        CP_COMMIT();     // empty group at tail keeps the wait trivial

        // compute stage c (load of c+1 overlaps this)
        const uint32_t stoff = (uint32_t)((c & 1) * STAGEB);
        #pragma unroll
        for (int ks = 0; ks < 2; ++ks) {
            uint32_t ah[4][4], al[4][4];
            #pragma unroll
            for (int mf = 0; mf < 4; ++mf) {
                ldsm_x4(ah[mf], aAddrH[mf] + stoff + ks * 32);
                ldsm_x4(al[mf], aAddrL[mf] + stoff + ks * 32);
            }
            #pragma unroll
            for (int np = 0; np < 2; ++np) {
                uint32_t bh[4], bl[4];
                ldsm_x4(bh, bAddrH[np] + stoff + ks * 32);
                ldsm_x4(bl, bAddrL[np] + stoff + ks * 32);
                #pragma unroll
                for (int half = 0; half < 2; ++half) {
                    const int nf = np * 2 + half;
                    const uint32_t bh0 = bh[half], bh1 = bh[half + 2];
                    const uint32_t bl0 = bl[half], bl1 = bl[half + 2];
                    #pragma unroll
                    for (int mf = 0; mf < 4; ++mf) {
                        mma_bf16(acc[mf][nf], ah[mf], bh0, bh1);
                        mma_bf16(acc[mf][nf], ah[mf], bl0, bl1);
                        mma_bf16(acc[mf][nf], al[mf], bh0, bh1);
                    }
                }
            }
        }

        CP_WAIT0();       // stage c+1 complete (this thread)
        __syncthreads();  // stage c+1 visible (all threads); buffer c free
    }

    // epilogue
    const int trow = lane >> 2;
    const int tcol = (lane & 3) * 2;
    #pragma unroll
    for (int mf = 0; mf < 4; ++mf) {
        #pragma unroll
        for (int nf = 0; nf < 4; ++nf) {
            const int r   = m0 + warp_m * 64 + mf * 16 + trow;
            const int col = n0 + warp_n * 32 + nf * 8 + tcol;
            const float b0 = bias[col], b1 = bias[col + 1];
            float2 v0, v1;
            v0.x = acc[mf][nf][0] + b0; v0.y = acc[mf][nf][1] + b1;
            v1.x = acc[mf][nf][2] + b0; v1.y = acc[mf][nf][3] + b1;
            *(float2*)&C[(size_t)r * N + col]       = v0;
            *(float2*)&C[(size_t)(r + 8) * N + col] = v1;
        }
    }
}

// ---------------- RMSNorm + RoPE, in place on q and k heads -----------------
__global__ __launch_bounds__(128) void norm_rope_kernel(
    const float* __restrict__ pe,
    const float* __restrict__ q_scale,
    const float* __restrict__ k_scale)
{
    const int t  = blockIdx.x;
    const int hh = blockIdx.y;
    const bool isK = hh >= N_HEADS;
    const int h  = hh & (N_HEADS - 1);
    const int d  = threadIdx.x;

    float* base = g_qkv + (size_t)t * QKV_COLS + (isK ? D_MODEL : 0) + h * D_HEAD;

    float v = base[d];
    float sq = v * v;
    #pragma unroll
    for (int o = 16; o > 0; o >>= 1)
        sq += __shfl_xor_sync(0xffffffffu, sq, o);

    __shared__ float red[4];
    __shared__ float sn[D_HEAD];
    const int wid = d >> 5;
    if ((d & 31) == 0) red[wid] = sq;
    __syncthreads();
    const float tot = red[0] + red[1] + red[2] + red[3];
    const float rrms = rsqrtf(tot * (1.f / D_HEAD) + EPS);

    const float* sc = isK ? k_scale : q_scale;
    sn[d] = v * rrms * sc[d];
    __syncthreads();

    const float c = pe[(size_t)t * 256 + (d & ~1)];
    const float s = pe[(size_t)t * 256 + 128 + (d & ~1)];
    const float v0 = sn[d & ~1];
    const float v1 = sn[d | 1];
    base[d] = (d & 1) ? (v0 * s + v1 * c) : (v0 * c - v1 * s);
}

// ---------------- flash-tile attention ------------------------------------
#define QS_STRIDE 72
#define PN_STRIDE 72

struct AttnSmem {
    float Qs[128 * QS_STRIDE];
    union {
        float Ks[128 * QS_STRIDE];
        float Vs[64 * 128];
    } kv;
    float Pn[64 * PN_STRIDE];
    float m[64], l[64], newm[64], cf[64];
};

__global__ __launch_bounds__(256, 2) void attn_tile_kernel(const int* __restrict__ seq_lens)
{
    extern __shared__ char smem_raw[];
    AttnSmem& S = *reinterpret_cast<AttnSmem*>(smem_raw);

    const int tid = threadIdx.x;
    const int tx = tid & 15;
    const int ty = tid >> 4;
    const int qt = blockIdx.x;
    const int h  = blockIdx.y;
    const int q0 = qt * 64;
    const int r0 = ty * 4;
    const int c0 = tx * 4;

    int start = 0, len = 0;
    #pragma unroll
    for (int i = 0; i < 4; ++i) {
        len = seq_lens[i];
        if (q0 < start + len) break;
        start += len;
    }
    const int end = start + len;

    for (int e = tid; e < 64 * 128; e += 256) {
        const int r = e >> 7, d = e & 127;
        S.Qs[d * QS_STRIDE + r] =
            g_qkv[(size_t)(q0 + r) * QKV_COLS + h * D_HEAD + d];
    }
    if (tid < 64) { S.m[tid] = -INFINITY; S.l[tid] = 0.f; }

    float o[4][8];
    #pragma unroll
    for (int i = 0; i < 4; ++i)
        #pragma unroll
        for (int c = 0; c < 8; ++c) o[i][c] = 0.f;

    for (int j0 = start; j0 < end; j0 += 64) {
        __syncthreads();

        for (int e = tid; e < 64 * 128; e += 256) {
            const int r = e >> 7, d = e & 127;
            S.kv.Ks[d * QS_STRIDE + r] =
                g_qkv[(size_t)(j0 + r) * QKV_COLS + D_MODEL + h * D_HEAD + d];
        }
        __syncthreads();

        float s[4][4];
        #pragma unroll
        for (int i = 0; i < 4; ++i)
            #pragma unroll
            for (int j = 0; j < 4; ++j) s[i][j] = 0.f;

        #pragma unroll 8
        for (int kk = 0; kk < 128; ++kk) {
            const float4 a = *(const float4*)&S.Qs[kk * QS_STRIDE + r0];
            const float4 b = *(const float4*)&S.kv.Ks[kk * QS_STRIDE + c0];
            const float av[4] = {a.x, a.y, a.z, a.w};
            const float bv[4] = {b.x, b.y, b.z, b.w};
            #pragma unroll
            for (int i = 0; i < 4; ++i)
                #pragma unroll
                for (int j = 0; j < 4; ++j)
                    s[i][j] = fmaf(av[i], bv[j], s[i][j]);
        }
        #pragma unroll
        for (int i = 0; i < 4; ++i)
            #pragma unroll
            for (int j = 0; j < 4; ++j) s[i][j] *= SM_SCALE;

        float rmax[4];
        #pragma unroll
        for (int i = 0; i < 4; ++i) {
            float v = fmaxf(fmaxf(s[i][0], s[i][1]), fmaxf(s[i][2], s[i][3]));
            #pragma unroll
            for (int off = 8; off > 0; off >>= 1)
                v = fmaxf(v, __shfl_xor_sync(0xffffffffu, v, off));
            rmax[i] = v;
        }
        if (tx == 0) {
            #pragma unroll
            for (int i = 0; i < 4; ++i) {
                const float mo = S.m[r0 + i];
                const float mn = fmaxf(mo, rmax[i]);
                S.newm[r0 + i] = mn;
                S.cf[r0 + i]   = __expf(mo - mn);
                S.m[r0 + i]    = mn;
            }
        }
        __syncthreads();

        float rs[4];
        #pragma unroll
        for (int i = 0; i < 4; ++i) {
            const float mn = S.newm[r0 + i];
            #pragma unroll
            for (int j = 0; j < 4; ++j) s[i][j] = __expf(s[i][j] - mn);
            rs[i] = (s[i][0] + s[i][1]) + (s[i][2] + s[i][3]);
            #pragma unroll
            for (int off = 8; off > 0; off >>= 1)
                rs[i] += __shfl_xor_sync(0xffffffffu, rs[i], off);
        }
        if (tx == 0) {
            #pragma unroll
            for (int i = 0; i < 4; ++i)
                S.l[r0 + i] = S.l[r0 + i] * S.cf[r0 + i] + rs[i];
        }
        #pragma unroll
        for (int i = 0; i < 4; ++i) {
            float4 pv = make_float4(s[i][0], s[i][1], s[i][2], s[i][3]);
            *(float4*)&S.Pn[(r0 + i) * PN_STRIDE + c0] = pv;
        }
        for (int e = tid; e < 64 * 128; e += 256) {
            const int r = e >> 7, d = e & 127;
            S.kv.Vs[r * 128 + d] =
                g_qkv[(size_t)(j0 + r) * QKV_COLS + 2 * D_MODEL + h * D_HEAD + d];
        }
        __syncthreads();

        {
            float cfl[4];
            #pragma unroll
            for (int i = 0; i < 4; ++i) cfl[i] = S.cf[r0 + i];
            #pragma unroll
            for (int i = 0; i < 4; ++i)
                #pragma unroll
                for (int c = 0; c < 8; ++c) o[i][c] *= cfl[i];
        }

        for (int j = 0; j < 64; j += 4) {
            float p[4][4];
            #pragma unroll
            for (int i = 0; i < 4; ++i) {
                const float4 p4 = *(const float4*)&S.Pn[(r0 + i) * PN_STRIDE + j];
                p[i][0] = p4.x; p[i][1] = p4.y; p[i][2] = p4.z; p[i][3] = p4.w;
            }
            #pragma unroll
            for (int jj = 0; jj < 4; ++jj) {
                const float4 v0 = *(const float4*)&S.kv.Vs[(j + jj) * 128 + tx * 8];
                const float4 v1 = *(const float4*)&S.kv.Vs[(j + jj) * 128 + tx * 8 + 4];
                #pragma unroll
                for (int i = 0; i < 4; ++i) {
                    o[i][0] = fmaf(p[i][jj], v0.x, o[i][0]);
                    o[i][1] = fmaf(p[i][jj], v0.y, o[i][1]);
                    o[i][2] = fmaf(p[i][jj], v0.z, o[i][2]);
                    o[i][3] = fmaf(p[i][jj], v0.w, o[i][3]);
                    o[i][4] = fmaf(p[i][jj], v1.x, o[i][4]);
                    o[i][5] = fmaf(p[i][jj], v1.y, o[i][5]);
                    o[i][6] = fmaf(p[i][jj], v1.z, o[i][6]);
                    o[i][7] = fmaf(p[i][jj], v1.w, o[i][7]);
                }
            }
        }
    }

    #pragma unroll
    for (int i = 0; i < 4; ++i) {
        const float linv = 1.f / S.l[r0 + i];
        float* dst = g_attn + (size_t)(q0 + r0 + i) * D_MODEL + h * D_HEAD + tx * 8;
        float4 w0, w1;
        w0.x = o[i][0] * linv; w0.y = o[i][1] * linv;
        w0.z = o[i][2] * linv; w0.w = o[i][3] * linv;
        w1.x = o[i][4] * linv; w1.y = o[i][5] * linv;
        w1.z = o[i][6] * linv; w1.w = o[i][7] * linv;
        *(float4*)(dst)     = w0;
        *(float4*)(dst + 4) = w1;
    }
}

// ---------------------------------------------------------------------------
extern "C" void kernel_launch(void* const* d_in, const int* in_sizes, int n_in,
                              void* d_out, int out_size)
{
    const float* x        = (const float*)d_in[0];
    const float* pe       = (const float*)d_in[1];
    const int*   seq_lens = (const int*)  d_in[2];
    const float* qkv_w    = (const float*)d_in[3];
    const float* qkv_b    = (const float*)d_in[4];
    const float* q_scale  = (const float*)d_in[5];
    const float* k_scale  = (const float*)d_in[6];
    const float* proj_w   = (const float*)d_in[7];
    const float* proj_b   = (const float*)d_in[8];
    float* out = (float*)d_out;

    float *qkv_ptr = nullptr, *attn_ptr = nullptr;
    __nv_bfloat16 *xhi, *xlo, *wqh, *wql, *wph, *wpl, *ahi, *alo;
    cudaGetSymbolAddress((void**)&qkv_ptr,  g_qkv);
    cudaGetSymbolAddress((void**)&attn_ptr, g_attn);
    cudaGetSymbolAddress((void**)&xhi, g_xhi);
    cudaGetSymbolAddress((void**)&xlo, g_xlo);
    cudaGetSymbolAddress((void**)&wqh, g_wqkv_hi);
    cudaGetSymbolAddress((void**)&wql, g_wqkv_lo);
    cudaGetSymbolAddress((void**)&wph, g_wp_hi);
    cudaGetSymbolAddress((void**)&wpl, g_wp_lo);
    cudaGetSymbolAddress((void**)&ahi, g_ahi);
    cudaGetSymbolAddress((void**)&alo, g_alo);

    const int attn_smem = (int)sizeof(AttnSmem);
    cudaFuncSetAttribute(attn_tile_kernel,
                         cudaFuncAttributeMaxDynamicSharedMemorySize, attn_smem);
    cudaFuncSetAttribute(gemm_mma,
                         cudaFuncAttributeMaxDynamicSharedMemorySize, GEMM_SMEM);

    // 0) split inputs into bf16 hi/lo
    {
        const int n4x = (L_TOTAL * D_MODEL) / 4;      // 1M
        const int n4w = (QKV_COLS * D_MODEL) / 4;     // 3M
        split_bf16_kernel<<<n4x / 256, 256>>>(x, xhi, xlo, n4x);
        split_bf16_kernel<<<n4w / 256, 256>>>(qkv_w, wqh, wql, n4w);
        split_bf16_kernel<<<n4x / 256, 256>>>(proj_w, wph, wpl, n4x);
    }

    // 1) qkv = x @ qkv_w^T + qkv_b   (HMMA, split-bf16 3-pass, 2-stage async)
    gemm_mma<<<dim3(QKV_COLS / 128, L_TOTAL / 128), 256, GEMM_SMEM>>>(
        xhi, xlo, wqh, wql, qkv_b, qkv_ptr, QKV_COLS, D_MODEL);

    // 2) RMSNorm + RoPE in place on q, k
    norm_rope_kernel<<<dim3(L_TOTAL, 2 * N_HEADS), 128>>>(pe, q_scale, k_scale);

    // 3) block-diagonal flash-tile attention -> g_attn
    attn_tile_kernel<<<dim3(L_TOTAL / 64, N_HEADS), 256, attn_smem>>>(seq_lens);

    // 4) split attention output, then out = attn @ proj_w^T + proj_b
    {
        const int n4a = (L_TOTAL * D_MODEL) / 4;
        split_bf16_kernel<<<n4a / 256, 256>>>(attn_ptr, ahi, alo, n4a);
    }
    gemm_mma<<<dim3(D_MODEL / 128, L_TOTAL / 128), 256, GEMM_SMEM>>>(
        ahi, alo, wph, wpl, proj_b, out, D_MODEL, D_MODEL);
}